// round 1
// baseline (speedup 1.0000x reference)
#include <cuda_runtime.h>

// Problem constants
#define N_SPANS 1024
#define DIM     512
#define HID     150
#define WIN     250
#define OUTW    (WIN + 1)

// Tiling for the main pair kernel
#define BM 64        // j (antecedent window slot) tile
#define BN 160       // h tile (HID=150 padded to 160)
#define BK 16        // k tile
#define TM 4         // rows per thread
#define TN 10        // cols per thread
#define NTHREADS 256

// Dynamic smem layout (floats):
// gis[512] gias[160] b2s[160] w3s[160] smj[64] jrow[64](int)
// As[16*65] Bs[16*160] H1s[64*161]
#define SMEM_FLOATS (512 + 160 + 160 + 160 + 64 + 64 + (BK*(BM+1)) + (BK*BN) + (BM*(BN+1)))
#define SMEM_BYTES  (SMEM_FLOATS * 4)

// Scratch for per-span precomputed terms
__device__ float d_gia[N_SPANS * HID];  // g @ W1a + b1
__device__ float d_gjt[N_SPANS * HID];  // g @ W1b

// ---------------------------------------------------------------------------
// Stage 1: per-span GEMM terms. One block per span row.
// ---------------------------------------------------------------------------
__global__ void precompute_kernel(const float* __restrict__ g,
                                  const float* __restrict__ W1,
                                  const float* __restrict__ b1) {
    __shared__ float gs[DIM];
    const int row = blockIdx.x;
    for (int t = threadIdx.x; t < DIM; t += blockDim.x)
        gs[t] = g[(size_t)row * DIM + t];
    __syncthreads();

    for (int job = threadIdx.x; job < 2 * HID; job += blockDim.x) {
        const int h   = (job < HID) ? job : job - HID;
        const int off = (job < HID) ? 0 : DIM;   // W1a rows [0,512), W1b rows [512,1024)
        float acc = 0.f;
#pragma unroll 8
        for (int dd = 0; dd < DIM; dd++)
            acc += gs[dd] * W1[(size_t)(off + dd) * HID + h];
        if (job < HID) d_gia[row * HID + h] = acc + b1[h];
        else           d_gjt[row * HID + h] = acc;
    }
}

// ---------------------------------------------------------------------------
// Stage 2: main fused pair-MLP kernel.
// blockIdx.y = span i, blockIdx.x = 64-wide tile of window slots k.
// Layer1: C[m][n] = sum_d (g_i[d]*g_j(m)[d]) * W1c[d][n]  (register-tiled GEMM)
// Layer2: fused [64 x 150] @ W2, then dot with W3, masked write.
// ---------------------------------------------------------------------------
__global__ __launch_bounds__(NTHREADS, 2)
void pair_kernel(const float* __restrict__ g,
                 const float* __restrict__ sm,
                 const float* __restrict__ W1,
                 const float* __restrict__ W2,
                 const float* __restrict__ b2,
                 const float* __restrict__ W3,
                 const float* __restrict__ b3,
                 float* __restrict__ out) {
    extern __shared__ float smemf[];
    float* gis  = smemf;                    // 512
    float* gias = gis + DIM;                // 160
    float* b2s  = gias + BN;                // 160
    float* w3s  = b2s + BN;                 // 160
    float* smj  = w3s + BN;                 // 64
    int*   jrow = (int*)(smj + BM);         // 64
    float* As   = (float*)(jrow + BM);      // 16 x 65
    float* Bs   = As + BK * (BM + 1);       // 16 x 160
    float* H1s  = Bs + BK * BN;             // 64 x 161

    const int i   = blockIdx.y;
    const int k0  = blockIdx.x * BM;
    const int tid = threadIdx.x;
    const int tx  = tid & 15;       // n direction
    const int ty  = tid >> 4;       // m direction

    // --- preload block-invariant data ---
    for (int t = tid; t < DIM; t += NTHREADS) gis[t] = g[(size_t)i * DIM + t];
    for (int t = tid; t < BN; t += NTHREADS) {
        const bool v = (t < HID);
        gias[t] = v ? d_gia[i * HID + t] : 0.f;
        b2s[t]  = v ? b2[t] : 0.f;
        w3s[t]  = v ? W3[t] : 0.f;
    }
    if (tid < BM) {
        int k = k0 + tid;
        int j = i - WIN + k;
        int jc = j < 0 ? 0 : (j > N_SPANS - 1 ? N_SPANS - 1 : j);
        jrow[tid] = jc;
        smj[tid]  = sm[jc];
    }
    const float sm_i = sm[i];
    const float b3v  = b3[0];
    __syncthreads();

    const float* W1c = W1 + (size_t)2 * DIM * HID;  // rows [1024, 1536)

    // --- Layer 1 GEMM: acc[m][n] over K = DIM ---
    float acc[TM][TN];
#pragma unroll
    for (int a = 0; a < TM; a++)
#pragma unroll
        for (int b = 0; b < TN; b++) acc[a][b] = 0.f;

    for (int dk = 0; dk < DIM; dk += BK) {
        // A tile: As[kk][m] = g_i[dk+kk] * g[j(m)][dk+kk]
        {
            const int kk = tid & 15, m0 = tid >> 4;
            const float gi_v = gis[dk + kk];
#pragma unroll
            for (int r = 0; r < 4; r++) {
                const int m = m0 + 16 * r;
                As[kk * (BM + 1) + m] = gi_v * g[(size_t)jrow[m] * DIM + dk + kk];
            }
        }
        // B tile: Bs[kk][n] = W1c[dk+kk][n] (n >= HID padded with 0)
#pragma unroll
        for (int r = 0; r < 10; r++) {
            const int idx = tid + r * NTHREADS;
            const int kk = idx / BN, n = idx % BN;
            Bs[kk * BN + n] = (n < HID) ? W1c[(size_t)(dk + kk) * HID + n] : 0.f;
        }
        __syncthreads();

#pragma unroll
        for (int kk = 0; kk < BK; kk++) {
            float a[TM], b[TN];
#pragma unroll
            for (int tm = 0; tm < TM; tm++) a[tm] = As[kk * (BM + 1) + tm * 16 + ty];
#pragma unroll
            for (int tn = 0; tn < TN; tn++) b[tn] = Bs[kk * BN + tn * 16 + tx];
#pragma unroll
            for (int tm = 0; tm < TM; tm++)
#pragma unroll
                for (int tn = 0; tn < TN; tn++)
                    acc[tm][tn] += a[tm] * b[tn];
        }
        __syncthreads();
    }

    // --- Layer 1 epilogue: h1 = relu(acc + gia_i + gjt_j + b1) -> H1s ---
#pragma unroll
    for (int tm = 0; tm < TM; tm++) {
        const int m = tm * 16 + ty;
        const int jc = jrow[m];
#pragma unroll
        for (int tn = 0; tn < TN; tn++) {
            const int n = tn * 16 + tx;
            float v = 0.f;
            if (n < HID) {
                v = acc[tm][tn] + gias[n] + d_gjt[jc * HID + n];
                v = fmaxf(v, 0.f);
            }
            H1s[m * (BN + 1) + n] = v;
        }
    }
    __syncthreads();

    // --- Layer 2 GEMM: acc2[m][n] = sum_k H1s[m][k] * W2[k][n] ---
    float acc2[TM][TN];
#pragma unroll
    for (int a = 0; a < TM; a++)
#pragma unroll
        for (int b = 0; b < TN; b++) acc2[a][b] = 0.f;

    for (int dk = 0; dk < BN; dk += BK) {
#pragma unroll
        for (int r = 0; r < 10; r++) {
            const int idx = tid + r * NTHREADS;
            const int kk = idx / BN, n = idx % BN;
            const int kg = dk + kk;
            Bs[kk * BN + n] = (kg < HID && n < HID) ? W2[(size_t)kg * HID + n] : 0.f;
        }
        __syncthreads();

#pragma unroll
        for (int kk = 0; kk < BK; kk++) {
            float a[TM], b[TN];
#pragma unroll
            for (int tm = 0; tm < TM; tm++) a[tm] = H1s[(tm * 16 + ty) * (BN + 1) + dk + kk];
#pragma unroll
            for (int tn = 0; tn < TN; tn++) b[tn] = Bs[kk * BN + tn * 16 + tx];
#pragma unroll
            for (int tm = 0; tm < TM; tm++)
#pragma unroll
                for (int tn = 0; tn < TN; tn++)
                    acc2[tm][tn] += a[tm] * b[tn];
        }
        __syncthreads();
    }

    // --- Layer 2 epilogue: s = relu(acc2 + b2) . W3, reduce over tx, write ---
#pragma unroll
    for (int tm = 0; tm < TM; tm++) {
        float p = 0.f;
#pragma unroll
        for (int tn = 0; tn < TN; tn++) {
            const int n = tn * 16 + tx;
            const float h2 = fmaxf(acc2[tm][tn] + b2s[n], 0.f);  // padded cols give 0
            p += h2 * w3s[n];
        }
        p += __shfl_down_sync(0xffffffffu, p, 8, 16);
        p += __shfl_down_sync(0xffffffffu, p, 4, 16);
        p += __shfl_down_sync(0xffffffffu, p, 2, 16);
        p += __shfl_down_sync(0xffffffffu, p, 1, 16);
        if (tx == 0) {
            const int m = tm * 16 + ty;
            const int k = k0 + m;
            if (k < WIN) {
                const int j = i - WIN + k;
                const float val = (j >= 0) ? (sm_i + smj[m] + p + b3v) : 0.f;
                out[i * OUTW + k] = val;
            } else if (k == WIN) {
                out[i * OUTW + k] = 0.f;  // trailing epsilon column
            }
        }
    }
}

// ---------------------------------------------------------------------------
extern "C" void kernel_launch(void* const* d_in, const int* in_sizes, int n_in,
                              void* d_out, int out_size) {
    const float* g  = (const float*)d_in[0];
    const float* sm = (const float*)d_in[1];
    const float* W1 = (const float*)d_in[2];
    const float* b1 = (const float*)d_in[3];
    const float* W2 = (const float*)d_in[4];
    const float* b2 = (const float*)d_in[5];
    const float* W3 = (const float*)d_in[6];
    const float* b3 = (const float*)d_in[7];
    float* out = (float*)d_out;

    // Idempotent, non-stream host call: legal under graph capture.
    cudaFuncSetAttribute(pair_kernel, cudaFuncAttributeMaxDynamicSharedMemorySize,
                         SMEM_BYTES);

    precompute_kernel<<<N_SPANS, NTHREADS>>>(g, W1, b1);
    pair_kernel<<<dim3(4, N_SPANS), NTHREADS, SMEM_BYTES>>>(g, sm, W1, W2, b2, W3, b3, out);
}

// round 3
// speedup vs baseline: 4.1022x; 4.1022x over previous
#include <cuda_runtime.h>
#include <cuda_bf16.h>
#include <stdint.h>

// ---------------- problem constants ----------------
#define N_SPANS 1024
#define DIM     512
#define HID     150
#define WIN     250
#define OUTW    (WIN + 1)
#define HPAD    160
#define NTHREADS 256

// row strides (bytes) for bf16 tiles
#define RS1 144        // layer-1 A and all B chunks: 64 bf16 + pad
#define RS2 336        // layer-2 A (h1): 160 bf16 + pad
#define BCHUNK_BYTES (HPAD * RS1)   // 23040 per split per chunk

// ---------------- smem layout (bytes) ----------------
#define OFF_JROW 0
#define OFF_SMJ  512
#define OFF_GIS  1024
#define OFF_GIAS 3072
#define OFF_B2S  3712
#define OFF_W3S  4352
#define OFF_SRED 4992               // 2 x 128 floats
#define OFF_A_HI 6144               // 128 x RS1
#define OFF_A_LO (OFF_A_HI + 128*RS1)
#define OFF_B_HI (OFF_A_LO + 128*RS1)          // 43008
#define OFF_B_LO (OFF_B_HI + BCHUNK_BYTES)
#define OFF_GJ   (OFF_B_LO + BCHUNK_BYTES)     // 89088, 128 x 608
#define OFF_A2_HI OFF_GJ                        // aliases gjt (write after sync)
#define OFF_A2_LO (OFF_A2_HI + 128*RS2)
#define SMEM_TOTAL (OFF_A2_LO + 128*RS2)        // 175104

// ---------------- device scratch ----------------
__device__ float d_gia[N_SPANS * HID];          // g@W1a + b1
__device__ float d_gjt[N_SPANS * 152];          // g@W1b, padded rows (16B-aligned)
__device__ unsigned char d_w1t_hi[8 * BCHUNK_BYTES];
__device__ unsigned char d_w1t_lo[8 * BCHUNK_BYTES];
__device__ unsigned char d_w2t_hi[3 * BCHUNK_BYTES];
__device__ unsigned char d_w2t_lo[3 * BCHUNK_BYTES];

// ---------------- helpers ----------------
__device__ __forceinline__ uint32_t packbf2(float a, float b) {
    __nv_bfloat162 t;
    t.x = __float2bfloat16(a);
    t.y = __float2bfloat16(b);
    return *reinterpret_cast<uint32_t*>(&t);
}
// split pair: returns hi bf16x2, computes residuals
__device__ __forceinline__ uint32_t split2(float a, float b, float& ra, float& rb) {
    __nv_bfloat16 ha = __float2bfloat16(a), hb = __float2bfloat16(b);
    ra = a - __bfloat162float(ha);
    rb = b - __bfloat162float(hb);
    __nv_bfloat162 t; t.x = ha; t.y = hb;
    return *reinterpret_cast<uint32_t*>(&t);
}

__device__ __forceinline__ void mma16816(float* c, const uint32_t* a,
                                         uint32_t b0, uint32_t b1) {
    asm volatile(
        "mma.sync.aligned.m16n8k16.row.col.f32.bf16.bf16.f32 "
        "{%0,%1,%2,%3}, {%4,%5,%6,%7}, {%8,%9}, {%0,%1,%2,%3};"
        : "+f"(c[0]), "+f"(c[1]), "+f"(c[2]), "+f"(c[3])
        : "r"(a[0]), "r"(a[1]), "r"(a[2]), "r"(a[3]), "r"(b0), "r"(b1));
}

// ---------------------------------------------------------------------------
// Stage 1a: per-span gia/gjt terms
// ---------------------------------------------------------------------------
__global__ void precompute_kernel(const float* __restrict__ g,
                                  const float* __restrict__ W1,
                                  const float* __restrict__ b1) {
    __shared__ float gs[DIM];
    const int row = blockIdx.x;
    for (int t = threadIdx.x; t < DIM; t += blockDim.x)
        gs[t] = g[(size_t)row * DIM + t];
    __syncthreads();
    if (threadIdx.x < 2) d_gjt[row * 152 + HID + threadIdx.x] = 0.f;  // pad cols
    for (int job = threadIdx.x; job < 2 * HID; job += blockDim.x) {
        const int h   = (job < HID) ? job : job - HID;
        const int off = (job < HID) ? 0 : DIM;
        float acc = 0.f;
#pragma unroll 8
        for (int dd = 0; dd < DIM; dd++)
            acc += gs[dd] * W1[(size_t)(off + dd) * HID + h];
        if (job < HID) d_gia[row * HID + h] = acc + b1[h];
        else           d_gjt[row * 152 + h] = acc;
    }
}

// ---------------------------------------------------------------------------
// Stage 1b: weight prep — W1c^T and W2^T, split hi/lo, chunked [c][n][64k]
// ---------------------------------------------------------------------------
__global__ void wprep_kernel(const float* __restrict__ W1,
                             const float* __restrict__ W2) {
    const int idx = blockIdx.x * blockDim.x + threadIdx.x;
    const int NW1 = 8 * HPAD * 64;
    if (idx < NW1) {
        const int c = idx / (HPAD * 64), r = idx % (HPAD * 64), n = r / 64, k = r % 64;
        const int d = c * 64 + k;
        const float v = (n < HID) ? W1[(size_t)(2 * DIM + d) * HID + n] : 0.f;
        __nv_bfloat16 hi = __float2bfloat16(v);
        __nv_bfloat16 lo = __float2bfloat16(v - __bfloat162float(hi));
        const uint32_t off = c * BCHUNK_BYTES + n * RS1 + k * 2;
        *(__nv_bfloat16*)(d_w1t_hi + off) = hi;
        *(__nv_bfloat16*)(d_w1t_lo + off) = lo;
    } else if (idx < NW1 + 3 * HPAD * 64) {
        const int i2 = idx - NW1;
        const int c = i2 / (HPAD * 64), r = i2 % (HPAD * 64), n = r / 64, k = r % 64;
        const int kk = c * 64 + k;
        const float v = (n < HID && kk < HID) ? W2[(size_t)kk * HID + n] : 0.f;
        __nv_bfloat16 hi = __float2bfloat16(v);
        __nv_bfloat16 lo = __float2bfloat16(v - __bfloat162float(hi));
        const uint32_t off = c * BCHUNK_BYTES + n * RS1 + k * 2;
        *(__nv_bfloat16*)(d_w2t_hi + off) = hi;
        *(__nv_bfloat16*)(d_w2t_lo + off) = lo;
    }
}

// ---------------------------------------------------------------------------
// Stage 2: mma.sync pair MLP. CTA = (span i, 128 window rows). 8 warps 4Mx2N.
// ---------------------------------------------------------------------------
__global__ __launch_bounds__(NTHREADS, 1)
void pair_mma_kernel(const float* __restrict__ g,
                     const float* __restrict__ sm,
                     const float* __restrict__ b2,
                     const float* __restrict__ W3,
                     const float* __restrict__ b3,
                     float* __restrict__ out) {
    extern __shared__ unsigned char smem[];
    const int tid  = threadIdx.x;
    const int wid  = tid >> 5, lane = tid & 31;
    const int g8   = lane >> 2, tig = lane & 3;
    const int wm   = wid & 3, wn = wid >> 2;
    const int i    = blockIdx.y;
    const int k0   = blockIdx.x * 128;

    int*   jrow = (int*)(smem + OFF_JROW);
    float* smjf = (float*)(smem + OFF_SMJ);
    float* gis  = (float*)(smem + OFF_GIS);
    float* gias = (float*)(smem + OFF_GIAS);
    float* b2s  = (float*)(smem + OFF_B2S);
    float* w3s  = (float*)(smem + OFF_W3S);
    float* sred = (float*)(smem + OFF_SRED);

    // ---- init ----
    for (int t = tid; t < DIM; t += NTHREADS) gis[t] = g[(size_t)i * DIM + t];
    if (tid < HPAD) {
        const bool v = tid < HID;
        gias[tid] = v ? d_gia[i * HID + tid] : 0.f;
        b2s[tid]  = v ? b2[tid] : 0.f;
        w3s[tid]  = v ? W3[tid] : 0.f;
    }
    if (tid < 128) {
        const int k = k0 + tid;
        int j = i - WIN + k;
        int jc = j < 0 ? 0 : (j > N_SPANS - 1 ? N_SPANS - 1 : j);
        jrow[tid] = jc;
        smjf[tid] = sm[jc];
    }
    __syncthreads();

    // ---- stage gjt tile (consumed after layer-1; overlaps compute) ----
    {
        const int m = tid >> 1, half = tid & 1;
        const uint4* src = (const uint4*)(d_gjt + jrow[m] * 152) + half * 19;
        uint4* dst = (uint4*)(smem + OFF_GJ + m * 608) + half * 19;
#pragma unroll
        for (int r = 0; r < 19; r++) dst[r] = src[r];
    }

    float acc[2][10][4];
#pragma unroll
    for (int a = 0; a < 2; a++)
#pragma unroll
        for (int b = 0; b < 10; b++)
#pragma unroll
            for (int e = 0; e < 4; e++) acc[a][b][e] = 0.f;

    const int bm  = tid >> 1;           // build row
    const int bkh = (tid & 1) * 32;     // build k-half
    const int jcm = jrow[bm];
    const int rowA = wm * 32 + g8;      // warp's base A row (mf adds 16)

    // ================= layer 1: K=512, 8 chunks of 64 =================
    for (int c = 0; c < 8; c++) {
        if (c) __syncthreads();   // prior mma must finish before overwrite
        // build A chunk: A[m][k] = gi[k]*gj[k], split hi/lo
        {
            const float4* gj4 = (const float4*)(g + (size_t)jcm * DIM + c * 64 + bkh);
            const float4* gi4 = (const float4*)(gis + c * 64 + bkh);
            unsigned char* ah = smem + OFF_A_HI + bm * RS1 + bkh * 2;
            unsigned char* al = smem + OFF_A_LO + bm * RS1 + bkh * 2;
#pragma unroll
            for (int v = 0; v < 8; v++) {
                const float4 a4 = gj4[v], i4 = gi4[v];
                float p0 = a4.x * i4.x, p1 = a4.y * i4.y;
                float p2 = a4.z * i4.z, p3 = a4.w * i4.w;
                float r0, r1, r2, r3;
                uint2 uh, ul;
                uh.x = split2(p0, p1, r0, r1);
                uh.y = split2(p2, p3, r2, r3);
                ul.x = packbf2(r0, r1);
                ul.y = packbf2(r2, r3);
                *(uint2*)(ah + v * 8) = uh;
                *(uint2*)(al + v * 8) = ul;
            }
        }
        // copy B chunk (pre-split W1c^T)
        {
            const uint4* sh = (const uint4*)(d_w1t_hi + c * BCHUNK_BYTES);
            const uint4* sl = (const uint4*)(d_w1t_lo + c * BCHUNK_BYTES);
            uint4* dh = (uint4*)(smem + OFF_B_HI);
            uint4* dl = (uint4*)(smem + OFF_B_LO);
#pragma unroll
            for (int r = 0; r < 6; r++) {
                const int ix = tid + r * NTHREADS;
                if (ix < BCHUNK_BYTES / 16) { dh[ix] = sh[ix]; dl[ix] = sl[ix]; }
            }
        }
        __syncthreads();
        // mma over 4 k16 steps
#pragma unroll
        for (int ks = 0; ks < 4; ks++) {
            const int koff = ks * 32 + tig * 4;  // bytes within row
            uint32_t Ah[2][4], Al[2][4];
#pragma unroll
            for (int mf = 0; mf < 2; mf++) {
                const unsigned char* ph = smem + OFF_A_HI + (rowA + mf * 16) * RS1 + koff;
                const unsigned char* pl = smem + OFF_A_LO + (rowA + mf * 16) * RS1 + koff;
                Ah[mf][0] = *(const uint32_t*)(ph);
                Ah[mf][1] = *(const uint32_t*)(ph + 8 * RS1);
                Ah[mf][2] = *(const uint32_t*)(ph + 16);
                Ah[mf][3] = *(const uint32_t*)(ph + 8 * RS1 + 16);
                Al[mf][0] = *(const uint32_t*)(pl);
                Al[mf][1] = *(const uint32_t*)(pl + 8 * RS1);
                Al[mf][2] = *(const uint32_t*)(pl + 16);
                Al[mf][3] = *(const uint32_t*)(pl + 8 * RS1 + 16);
            }
#pragma unroll
            for (int nf = 0; nf < 10; nf++) {
                const int rowB = wn * 80 + nf * 8 + g8;
                const unsigned char* pbh = smem + OFF_B_HI + rowB * RS1 + koff;
                const unsigned char* pbl = smem + OFF_B_LO + rowB * RS1 + koff;
                const uint32_t bh0 = *(const uint32_t*)(pbh);
                const uint32_t bh1 = *(const uint32_t*)(pbh + 16);
                const uint32_t bl0 = *(const uint32_t*)(pbl);
                const uint32_t bl1 = *(const uint32_t*)(pbl + 16);
#pragma unroll
                for (int mf = 0; mf < 2; mf++) {
                    mma16816(acc[mf][nf], Ah[mf], bh0, bh1);
                    mma16816(acc[mf][nf], Al[mf], bh0, bh1);
                    mma16816(acc[mf][nf], Ah[mf], bl0, bl1);
                }
            }
        }
    }

    // ---- layer-1 epilogue: h1 = relu(acc + gia + gjt) (in place) ----
#pragma unroll
    for (int mf = 0; mf < 2; mf++) {
        const int r = rowA + mf * 16;
#pragma unroll
        for (int nf = 0; nf < 10; nf++) {
            const int n0 = wn * 80 + nf * 8 + tig * 2;
            if (n0 < HID) {
                const float2 ga = *(const float2*)(gias + n0);
                const float2 gj0 = *(const float2*)(smem + OFF_GJ + r * 608 + n0 * 4);
                const float2 gj1 = *(const float2*)(smem + OFF_GJ + (r + 8) * 608 + n0 * 4);
                acc[mf][nf][0] = fmaxf(acc[mf][nf][0] + gj0.x + ga.x, 0.f);
                acc[mf][nf][1] = fmaxf(acc[mf][nf][1] + gj0.y + ga.y, 0.f);
                acc[mf][nf][2] = fmaxf(acc[mf][nf][2] + gj1.x + ga.x, 0.f);
                acc[mf][nf][3] = fmaxf(acc[mf][nf][3] + gj1.y + ga.y, 0.f);
            } else {
                acc[mf][nf][0] = acc[mf][nf][1] = acc[mf][nf][2] = acc[mf][nf][3] = 0.f;
            }
        }
    }
    __syncthreads();   // all gjt reads done before A2 overwrites that region

    // ---- write h1 split tiles into A2 ----
#pragma unroll
    for (int mf = 0; mf < 2; mf++) {
        const int r = rowA + mf * 16;
#pragma unroll
        for (int nf = 0; nf < 10; nf++) {
            const int n0 = wn * 80 + nf * 8 + tig * 2;
            float r0, r1;
            uint32_t h = split2(acc[mf][nf][0], acc[mf][nf][1], r0, r1);
            *(uint32_t*)(smem + OFF_A2_HI + r * RS2 + n0 * 2) = h;
            *(uint32_t*)(smem + OFF_A2_LO + r * RS2 + n0 * 2) = packbf2(r0, r1);
            h = split2(acc[mf][nf][2], acc[mf][nf][3], r0, r1);
            *(uint32_t*)(smem + OFF_A2_HI + (r + 8) * RS2 + n0 * 2) = h;
            *(uint32_t*)(smem + OFF_A2_LO + (r + 8) * RS2 + n0 * 2) = packbf2(r0, r1);
        }
    }

#pragma unroll
    for (int a = 0; a < 2; a++)
#pragma unroll
        for (int b = 0; b < 10; b++)
#pragma unroll
            for (int e = 0; e < 4; e++) acc[a][b][e] = 0.f;

    // ================= layer 2: K=160 (3 chunks: 64,64,32) =================
    for (int c2 = 0; c2 < 3; c2++) {
        __syncthreads();   // A2 writes (c2==0) / prior mma B reads done
        {
            const uint4* sh = (const uint4*)(d_w2t_hi + c2 * BCHUNK_BYTES);
            const uint4* sl = (const uint4*)(d_w2t_lo + c2 * BCHUNK_BYTES);
            uint4* dh = (uint4*)(smem + OFF_B_HI);
            uint4* dl = (uint4*)(smem + OFF_B_LO);
#pragma unroll
            for (int r = 0; r < 6; r++) {
                const int ix = tid + r * NTHREADS;
                if (ix < BCHUNK_BYTES / 16) { dh[ix] = sh[ix]; dl[ix] = sl[ix]; }
            }
        }
        __syncthreads();
        const int nks = (c2 < 2) ? 4 : 2;
        for (int ks = 0; ks < nks; ks++) {
            const int kbyte = (c2 * 64 + ks * 16 + tig * 2) * 2;
            const int koff = ks * 32 + tig * 4;
            uint32_t Ah[2][4], Al[2][4];
#pragma unroll
            for (int mf = 0; mf < 2; mf++) {
                const unsigned char* ph = smem + OFF_A2_HI + (rowA + mf * 16) * RS2 + kbyte;
                const unsigned char* pl = smem + OFF_A2_LO + (rowA + mf * 16) * RS2 + kbyte;
                Ah[mf][0] = *(const uint32_t*)(ph);
                Ah[mf][1] = *(const uint32_t*)(ph + 8 * RS2);
                Ah[mf][2] = *(const uint32_t*)(ph + 16);
                Ah[mf][3] = *(const uint32_t*)(ph + 8 * RS2 + 16);
                Al[mf][0] = *(const uint32_t*)(pl);
                Al[mf][1] = *(const uint32_t*)(pl + 8 * RS2);
                Al[mf][2] = *(const uint32_t*)(pl + 16);
                Al[mf][3] = *(const uint32_t*)(pl + 8 * RS2 + 16);
            }
#pragma unroll
            for (int nf = 0; nf < 10; nf++) {
                const int rowB = wn * 80 + nf * 8 + g8;
                const unsigned char* pbh = smem + OFF_B_HI + rowB * RS1 + koff;
                const unsigned char* pbl = smem + OFF_B_LO + rowB * RS1 + koff;
                const uint32_t bh0 = *(const uint32_t*)(pbh);
                const uint32_t bh1 = *(const uint32_t*)(pbh + 16);
                const uint32_t bl0 = *(const uint32_t*)(pbl);
                const uint32_t bl1 = *(const uint32_t*)(pbl + 16);
#pragma unroll
                for (int mf = 0; mf < 2; mf++) {
                    mma16816(acc[mf][nf], Ah[mf], bh0, bh1);
                    mma16816(acc[mf][nf], Al[mf], bh0, bh1);
                    mma16816(acc[mf][nf], Ah[mf], bl0, bl1);
                }
            }
        }
    }

    // ---- final: s = relu(acc2 + b2) . W3, quad-shuffle reduce ----
#pragma unroll
    for (int mf = 0; mf < 2; mf++) {
        float pr = 0.f, pr8 = 0.f;
#pragma unroll
        for (int nf = 0; nf < 10; nf++) {
            const int n0 = wn * 80 + nf * 8 + tig * 2;
            const float2 bb = *(const float2*)(b2s + n0);
            const float2 ww = *(const float2*)(w3s + n0);
            pr  += fmaxf(acc[mf][nf][0] + bb.x, 0.f) * ww.x
                 + fmaxf(acc[mf][nf][1] + bb.y, 0.f) * ww.y;
            pr8 += fmaxf(acc[mf][nf][2] + bb.x, 0.f) * ww.x
                 + fmaxf(acc[mf][nf][3] + bb.y, 0.f) * ww.y;
        }
        pr  += __shfl_xor_sync(0xffffffffu, pr, 1);
        pr  += __shfl_xor_sync(0xffffffffu, pr, 2);
        pr8 += __shfl_xor_sync(0xffffffffu, pr8, 1);
        pr8 += __shfl_xor_sync(0xffffffffu, pr8, 2);
        if (tig == 0) {
            sred[wn * 128 + rowA + mf * 16]     = pr;
            sred[wn * 128 + rowA + mf * 16 + 8] = pr8;
        }
    }
    __syncthreads();

    if (tid < 128) {
        const float s = sred[tid] + sred[128 + tid];
        const int k = k0 + tid;
        if (k < WIN) {
            const int j = i - WIN + k;
            out[i * OUTW + k] = (j >= 0) ? (sm[i] + smjf[tid] + s + b3[0]) : 0.f;
        } else if (k == WIN) {
            out[i * OUTW + k] = 0.f;  // trailing epsilon column
        }
    }
}

// ---------------------------------------------------------------------------
extern "C" void kernel_launch(void* const* d_in, const int* in_sizes, int n_in,
                              void* d_out, int out_size) {
    const float* g  = (const float*)d_in[0];
    const float* sm = (const float*)d_in[1];
    const float* W1 = (const float*)d_in[2];
    const float* b1 = (const float*)d_in[3];
    const float* W2 = (const float*)d_in[4];
    const float* b2 = (const float*)d_in[5];
    const float* W3 = (const float*)d_in[6];
    const float* b3 = (const float*)d_in[7];
    float* out = (float*)d_out;

    cudaFuncSetAttribute(pair_mma_kernel, cudaFuncAttributeMaxDynamicSharedMemorySize,
                         SMEM_TOTAL);

    precompute_kernel<<<N_SPANS, NTHREADS>>>(g, W1, b1);
    const int nprep = 8 * HPAD * 64 + 3 * HPAD * 64;
    wprep_kernel<<<(nprep + NTHREADS - 1) / NTHREADS, NTHREADS>>>(W1, W2);
    pair_mma_kernel<<<dim3(2, N_SPANS), NTHREADS, SMEM_TOTAL>>>(g, sm, b2, W3, b3, out);
}

// round 4
// speedup vs baseline: 4.7433x; 1.1563x over previous
#include <cuda_runtime.h>
#include <cuda_bf16.h>
#include <stdint.h>

// ---------------- problem constants ----------------
#define N_SPANS 1024
#define DIM     512
#define HID     150
#define WIN     250
#define OUTW    (WIN + 1)
#define HPAD    160
#define NTHREADS 256

// row strides (bytes) for bf16 tiles (multiples of 16 for ldmatrix)
#define RS1 144        // layer-1 A and all B chunks: 64 bf16 + pad
#define RS2 336        // layer-2 A (h1): 160 bf16 + pad
#define BCHUNK_BYTES (HPAD * RS1)   // 23040 per split per chunk
#define BCHUNK_V16   (BCHUNK_BYTES / 16)  // 1440

// ---------------- smem layout (bytes) ----------------
#define OFF_JROW 0
#define OFF_SMJ  512
#define OFF_GIS  1024
#define OFF_GIAS 3072
#define OFF_B2S  3712
#define OFF_W3S  4352
#define OFF_SRED 4992               // 2 x 128 floats
#define OFF_A_HI 6144               // 128 x RS1
#define OFF_A_LO (OFF_A_HI + 128*RS1)
#define OFF_B_HI (OFF_A_LO + 128*RS1)
#define OFF_B_LO (OFF_B_HI + BCHUNK_BYTES)
#define OFF_GJ   (OFF_B_LO + BCHUNK_BYTES)     // 128 x 608
#define OFF_A2_HI OFF_GJ                        // aliases gjt (write after sync)
#define OFF_A2_LO (OFF_A2_HI + 128*RS2)
#define SMEM_TOTAL (OFF_A2_LO + 128*RS2)        // 175104

// ---------------- device scratch ----------------
__device__ float d_gia[N_SPANS * HID];          // g@W1a + b1
__device__ float d_gjt[N_SPANS * 152];          // g@W1b, padded rows
__device__ unsigned char d_w1t_hi[8 * BCHUNK_BYTES];
__device__ unsigned char d_w1t_lo[8 * BCHUNK_BYTES];
__device__ unsigned char d_w2t_hi[3 * BCHUNK_BYTES];
__device__ unsigned char d_w2t_lo[3 * BCHUNK_BYTES];

// ---------------- helpers ----------------
__device__ __forceinline__ uint32_t smem_u32(const void* p) {
    uint32_t a;
    asm("{ .reg .u64 t; cvta.to.shared.u64 t, %1; cvt.u32.u64 %0, t; }" : "=r"(a) : "l"(p));
    return a;
}
__device__ __forceinline__ uint32_t packbf2(float a, float b) {
    __nv_bfloat162 t;
    t.x = __float2bfloat16(a);
    t.y = __float2bfloat16(b);
    return *reinterpret_cast<uint32_t*>(&t);
}
__device__ __forceinline__ uint32_t split2(float a, float b, float& ra, float& rb) {
    __nv_bfloat16 ha = __float2bfloat16(a), hb = __float2bfloat16(b);
    ra = a - __bfloat162float(ha);
    rb = b - __bfloat162float(hb);
    __nv_bfloat162 t; t.x = ha; t.y = hb;
    return *reinterpret_cast<uint32_t*>(&t);
}
__device__ __forceinline__ void mma16816(float* c, const uint32_t* a,
                                         uint32_t b0, uint32_t b1) {
    asm volatile(
        "mma.sync.aligned.m16n8k16.row.col.f32.bf16.bf16.f32 "
        "{%0,%1,%2,%3}, {%4,%5,%6,%7}, {%8,%9}, {%0,%1,%2,%3};"
        : "+f"(c[0]), "+f"(c[1]), "+f"(c[2]), "+f"(c[3])
        : "r"(a[0]), "r"(a[1]), "r"(a[2]), "r"(a[3]), "r"(b0), "r"(b1));
}
__device__ __forceinline__ void ldsm_x4(uint32_t* r, uint32_t addr) {
    asm volatile("ldmatrix.sync.aligned.m8n8.x4.shared.b16 {%0,%1,%2,%3}, [%4];"
        : "=r"(r[0]), "=r"(r[1]), "=r"(r[2]), "=r"(r[3]) : "r"(addr));
}
#define CPA16(dst, src) asm volatile("cp.async.ca.shared.global [%0], [%1], 16;" :: "r"(dst), "l"(src))
#define CPA_COMMIT()    asm volatile("cp.async.commit_group;" ::: "memory")
#define CPA_WAIT0()     asm volatile("cp.async.wait_group 0;" ::: "memory")

// ---------------------------------------------------------------------------
// Stage 1a: per-span gia/gjt terms — tiled smem GEMM.
// 128 blocks: blockIdx.x = mtile*2 + half (half 0 => gia, 1 => gjt).
// Block computes 16 rows x 150 cols, K=512 in chunks of 64.
// ---------------------------------------------------------------------------
__global__ __launch_bounds__(256)
void precompute_kernel(const float* __restrict__ g,
                       const float* __restrict__ W1,
                       const float* __restrict__ b1) {
    __shared__ float gs[16][64];
    __shared__ float Ws[64][HPAD];
    const int half = blockIdx.x & 1, mt = blockIdx.x >> 1;
    const int tid = threadIdx.x, tx = tid & 15, ty = tid >> 4;

    float acc[10];
#pragma unroll
    for (int j = 0; j < 10; j++) acc[j] = 0.f;

    for (int kc = 0; kc < 8; kc++) {
#pragma unroll
        for (int r = 0; r < 4; r++) {
            const int ix = tid + r * 256, rr = ix >> 6, kk = ix & 63;
            gs[rr][kk] = g[(size_t)(mt * 16 + rr) * DIM + kc * 64 + kk];
        }
#pragma unroll
        for (int r = 0; r < 40; r++) {
            const int ix = tid + r * 256, kk = ix / HPAD, nn = ix % HPAD;
            Ws[kk][nn] = (nn < HID)
                ? W1[(size_t)(half * DIM + kc * 64 + kk) * HID + nn] : 0.f;
        }
        __syncthreads();
#pragma unroll 8
        for (int k = 0; k < 64; k++) {
            const float a0 = gs[ty][k];
#pragma unroll
            for (int j = 0; j < 10; j++)
                acc[j] += a0 * Ws[k][tx + 16 * j];
        }
        __syncthreads();
    }

    const int row = mt * 16 + ty;
#pragma unroll
    for (int j = 0; j < 10; j++) {
        const int n = tx + 16 * j;
        if (n < HID) {
            if (!half) d_gia[row * HID + n] = acc[j] + b1[n];
            else       d_gjt[row * 152 + n] = acc[j];
        }
    }
    if (half && tx == 0) {
        d_gjt[row * 152 + 150] = 0.f;
        d_gjt[row * 152 + 151] = 0.f;
    }
}

// ---------------------------------------------------------------------------
// Stage 1b: weight prep — W1c^T and W2^T, split hi/lo, chunked [c][n][64k]
// ---------------------------------------------------------------------------
__global__ void wprep_kernel(const float* __restrict__ W1,
                             const float* __restrict__ W2) {
    const int idx = blockIdx.x * blockDim.x + threadIdx.x;
    const int NW1 = 8 * HPAD * 64;
    if (idx < NW1) {
        const int c = idx / (HPAD * 64), r = idx % (HPAD * 64), n = r / 64, k = r % 64;
        const int d = c * 64 + k;
        const float v = (n < HID) ? W1[(size_t)(2 * DIM + d) * HID + n] : 0.f;
        __nv_bfloat16 hi = __float2bfloat16(v);
        __nv_bfloat16 lo = __float2bfloat16(v - __bfloat162float(hi));
        const uint32_t off = c * BCHUNK_BYTES + n * RS1 + k * 2;
        *(__nv_bfloat16*)(d_w1t_hi + off) = hi;
        *(__nv_bfloat16*)(d_w1t_lo + off) = lo;
    } else if (idx < NW1 + 3 * HPAD * 64) {
        const int i2 = idx - NW1;
        const int c = i2 / (HPAD * 64), r = i2 % (HPAD * 64), n = r / 64, k = r % 64;
        const int kk = c * 64 + k;
        const float v = (n < HID && kk < HID) ? W2[(size_t)kk * HID + n] : 0.f;
        __nv_bfloat16 hi = __float2bfloat16(v);
        __nv_bfloat16 lo = __float2bfloat16(v - __bfloat162float(hi));
        const uint32_t off = c * BCHUNK_BYTES + n * RS1 + k * 2;
        *(__nv_bfloat16*)(d_w2t_hi + off) = hi;
        *(__nv_bfloat16*)(d_w2t_lo + off) = lo;
    }
}

// ---------------------------------------------------------------------------
// Stage 2: mma.sync pair MLP with ldmatrix + cp.async + gj register prefetch.
// CTA = (span i, 128 window rows). 8 warps as 4(M) x 2(N).
// ---------------------------------------------------------------------------
__global__ __launch_bounds__(NTHREADS, 1)
void pair_mma_kernel(const float* __restrict__ g,
                     const float* __restrict__ sm,
                     const float* __restrict__ b2,
                     const float* __restrict__ W3,
                     const float* __restrict__ b3,
                     float* __restrict__ out) {
    extern __shared__ unsigned char smem[];
    const uint32_t sbase = smem_u32(smem);
    const int tid  = threadIdx.x;
    const int wid  = tid >> 5, lane = tid & 31;
    const int g8   = lane >> 2, tig = lane & 3;
    const int wm   = wid & 3, wn = wid >> 2;
    const int i    = blockIdx.y;
    const int k0   = blockIdx.x * 128;

    int*   jrow = (int*)(smem + OFF_JROW);
    float* smjf = (float*)(smem + OFF_SMJ);
    float* gis  = (float*)(smem + OFF_GIS);
    float* gias = (float*)(smem + OFF_GIAS);
    float* b2s  = (float*)(smem + OFF_B2S);
    float* w3s  = (float*)(smem + OFF_W3S);
    float* sred = (float*)(smem + OFF_SRED);

    // ---- init ----
    for (int t = tid; t < DIM; t += NTHREADS) gis[t] = g[(size_t)i * DIM + t];
    if (tid < HPAD) {
        const bool v = tid < HID;
        gias[tid] = v ? d_gia[i * HID + tid] : 0.f;
        b2s[tid]  = v ? b2[tid] : 0.f;
        w3s[tid]  = v ? W3[tid] : 0.f;
    }
    if (tid < 128) {
        const int k = k0 + tid;
        int j = i - WIN + k;
        int jc = j < 0 ? 0 : (j > N_SPANS - 1 ? N_SPANS - 1 : j);
        jrow[tid] = jc;
        smjf[tid] = sm[jc];
    }
    __syncthreads();

    // ---- stage gjt tile (consumed after layer-1; overlaps compute) ----
    {
        const int m = tid >> 1, half = tid & 1;
        const uint4* src = (const uint4*)(d_gjt + jrow[m] * 152) + half * 19;
        uint4* dst = (uint4*)(smem + OFF_GJ + m * 608) + half * 19;
#pragma unroll
        for (int r = 0; r < 19; r++) dst[r] = src[r];
    }

    float acc[2][10][4];
#pragma unroll
    for (int a = 0; a < 2; a++)
#pragma unroll
        for (int b = 0; b < 10; b++)
#pragma unroll
            for (int e = 0; e < 4; e++) acc[a][b][e] = 0.f;

    const int bm  = tid >> 1;           // build row
    const int bkh = (tid & 1) * 32;     // build k-half (floats)
    const int jcm = jrow[bm];
    const int rowA = wm * 32 + g8;      // fragment base A row

    // ldmatrix lane addresses
    const uint32_t aAddrH  = sbase + OFF_A_HI + (wm * 32 + (lane & 15)) * RS1 + ((lane >> 4) << 4);
    const uint32_t aAddrL  = aAddrH + (OFF_A_LO - OFF_A_HI);
    const uint32_t a2AddrH = sbase + OFF_A2_HI + (wm * 32 + (lane & 15)) * RS2 + ((lane >> 4) << 4);
    const uint32_t a2AddrL = a2AddrH + (OFF_A2_LO - OFF_A2_HI);
    const uint32_t bAddrH  = sbase + OFF_B_HI +
        (wn * 80 + (lane & 7) + ((lane >> 4) << 3)) * RS1 + (((lane >> 3) & 1) << 4);
    const uint32_t bAddrL  = bAddrH + BCHUNK_BYTES;

    // prefetch gj chunk 0
    float4 pgj[8];
    {
        const float4* gj4 = (const float4*)(g + (size_t)jcm * DIM + bkh);
#pragma unroll
        for (int v = 0; v < 8; v++) pgj[v] = gj4[v];
    }

    // ================= layer 1: K=512, 8 chunks of 64 =================
    for (int c = 0; c < 8; c++) {
        if (c) __syncthreads();   // prior mma done before overwriting A/B
        // issue B chunk copy (cp.async)
        {
            const unsigned char* sh = d_w1t_hi + c * BCHUNK_BYTES;
            const unsigned char* sl = d_w1t_lo + c * BCHUNK_BYTES;
#pragma unroll
            for (int r = 0; r < 6; r++) {
                const int ix = tid + r * NTHREADS;
                if (ix < BCHUNK_V16) {
                    CPA16(sbase + OFF_B_HI + ix * 16, sh + ix * 16);
                    CPA16(sbase + OFF_B_LO + ix * 16, sl + ix * 16);
                }
            }
            CPA_COMMIT();
        }
        // build A chunk from prefetched regs
        {
            const float4* gi4 = (const float4*)(gis + c * 64 + bkh);
            unsigned char* ah = smem + OFF_A_HI + bm * RS1 + bkh * 2;
            unsigned char* al = smem + OFF_A_LO + bm * RS1 + bkh * 2;
#pragma unroll
            for (int v = 0; v < 8; v++) {
                const float4 a4 = pgj[v], i4 = gi4[v];
                float p0 = a4.x * i4.x, p1 = a4.y * i4.y;
                float p2 = a4.z * i4.z, p3 = a4.w * i4.w;
                float r0, r1, r2, r3;
                uint2 uh, ul;
                uh.x = split2(p0, p1, r0, r1);
                uh.y = split2(p2, p3, r2, r3);
                ul.x = packbf2(r0, r1);
                ul.y = packbf2(r2, r3);
                *(uint2*)(ah + v * 8) = uh;
                *(uint2*)(al + v * 8) = ul;
            }
        }
        // prefetch next gj chunk (completes under the mma below)
        if (c < 7) {
            const float4* gj4 = (const float4*)(g + (size_t)jcm * DIM + (c + 1) * 64 + bkh);
#pragma unroll
            for (int v = 0; v < 8; v++) pgj[v] = gj4[v];
        }
        CPA_WAIT0();
        __syncthreads();

        // mma over 4 k16 steps, ldmatrix fragments
#pragma unroll
        for (int ks = 0; ks < 4; ks++) {
            const uint32_t ko = ks * 32;
            uint32_t Ah0[4], Ah1[4], Al0[4], Al1[4];
            ldsm_x4(Ah0, aAddrH + ko);
            ldsm_x4(Ah1, aAddrH + 16 * RS1 + ko);
            ldsm_x4(Al0, aAddrL + ko);
            ldsm_x4(Al1, aAddrL + 16 * RS1 + ko);
#pragma unroll
            for (int p = 0; p < 5; p++) {
                uint32_t BH[4], BL[4];
                ldsm_x4(BH, bAddrH + p * 16 * RS1 + ko);
                ldsm_x4(BL, bAddrL + p * 16 * RS1 + ko);
                const int nA = 2 * p, nB = 2 * p + 1;
                mma16816(acc[0][nA], Ah0, BH[0], BH[1]);
                mma16816(acc[1][nA], Ah1, BH[0], BH[1]);
                mma16816(acc[0][nA], Al0, BH[0], BH[1]);
                mma16816(acc[1][nA], Al1, BH[0], BH[1]);
                mma16816(acc[0][nA], Ah0, BL[0], BL[1]);
                mma16816(acc[1][nA], Ah1, BL[0], BL[1]);
                mma16816(acc[0][nB], Ah0, BH[2], BH[3]);
                mma16816(acc[1][nB], Ah1, BH[2], BH[3]);
                mma16816(acc[0][nB], Al0, BH[2], BH[3]);
                mma16816(acc[1][nB], Al1, BH[2], BH[3]);
                mma16816(acc[0][nB], Ah0, BL[2], BL[3]);
                mma16816(acc[1][nB], Ah1, BL[2], BL[3]);
            }
        }
    }

    // ---- layer-1 epilogue: h1 = relu(acc + gia + gjt) (in registers) ----
#pragma unroll
    for (int mf = 0; mf < 2; mf++) {
        const int r = rowA + mf * 16;
#pragma unroll
        for (int nf = 0; nf < 10; nf++) {
            const int n0 = wn * 80 + nf * 8 + tig * 2;
            if (n0 < HID) {
                const float2 ga = *(const float2*)(gias + n0);
                const float2 gj0 = *(const float2*)(smem + OFF_GJ + r * 608 + n0 * 4);
                const float2 gj1 = *(const float2*)(smem + OFF_GJ + (r + 8) * 608 + n0 * 4);
                acc[mf][nf][0] = fmaxf(acc[mf][nf][0] + gj0.x + ga.x, 0.f);
                acc[mf][nf][1] = fmaxf(acc[mf][nf][1] + gj0.y + ga.y, 0.f);
                acc[mf][nf][2] = fmaxf(acc[mf][nf][2] + gj1.x + ga.x, 0.f);
                acc[mf][nf][3] = fmaxf(acc[mf][nf][3] + gj1.y + ga.y, 0.f);
            } else {
                acc[mf][nf][0] = acc[mf][nf][1] = acc[mf][nf][2] = acc[mf][nf][3] = 0.f;
            }
        }
    }
    __syncthreads();   // all gjt reads done before A2 overwrites that region

    // ---- write h1 split tiles into A2 ----
#pragma unroll
    for (int mf = 0; mf < 2; mf++) {
        const int r = rowA + mf * 16;
#pragma unroll
        for (int nf = 0; nf < 10; nf++) {
            const int n0 = wn * 80 + nf * 8 + tig * 2;
            float r0, r1;
            uint32_t h = split2(acc[mf][nf][0], acc[mf][nf][1], r0, r1);
            *(uint32_t*)(smem + OFF_A2_HI + r * RS2 + n0 * 2) = h;
            *(uint32_t*)(smem + OFF_A2_LO + r * RS2 + n0 * 2) = packbf2(r0, r1);
            h = split2(acc[mf][nf][2], acc[mf][nf][3], r0, r1);
            *(uint32_t*)(smem + OFF_A2_HI + (r + 8) * RS2 + n0 * 2) = h;
            *(uint32_t*)(smem + OFF_A2_LO + (r + 8) * RS2 + n0 * 2) = packbf2(r0, r1);
        }
    }

#pragma unroll
    for (int a = 0; a < 2; a++)
#pragma unroll
        for (int b = 0; b < 10; b++)
#pragma unroll
            for (int e = 0; e < 4; e++) acc[a][b][e] = 0.f;

    // ================= layer 2: K=160 (3 chunks: 64,64,32) =================
    for (int c2 = 0; c2 < 3; c2++) {
        __syncthreads();   // A2 writes (c2==0) / prior mma B reads done
        {
            const unsigned char* sh = d_w2t_hi + c2 * BCHUNK_BYTES;
            const unsigned char* sl = d_w2t_lo + c2 * BCHUNK_BYTES;
#pragma unroll
            for (int r = 0; r < 6; r++) {
                const int ix = tid + r * NTHREADS;
                if (ix < BCHUNK_V16) {
                    CPA16(sbase + OFF_B_HI + ix * 16, sh + ix * 16);
                    CPA16(sbase + OFF_B_LO + ix * 16, sl + ix * 16);
                }
            }
            CPA_COMMIT();
            CPA_WAIT0();
        }
        __syncthreads();
        const int nks = (c2 < 2) ? 4 : 2;
        for (int ks = 0; ks < nks; ks++) {
            const uint32_t ko  = ks * 32;
            const uint32_t ko2 = c2 * 128 + ks * 32;
            uint32_t Ah0[4], Ah1[4], Al0[4], Al1[4];
            ldsm_x4(Ah0, a2AddrH + ko2);
            ldsm_x4(Ah1, a2AddrH + 16 * RS2 + ko2);
            ldsm_x4(Al0, a2AddrL + ko2);
            ldsm_x4(Al1, a2AddrL + 16 * RS2 + ko2);
#pragma unroll
            for (int p = 0; p < 5; p++) {
                uint32_t BH[4], BL[4];
                ldsm_x4(BH, bAddrH + p * 16 * RS1 + ko);
                ldsm_x4(BL, bAddrL + p * 16 * RS1 + ko);
                const int nA = 2 * p, nB = 2 * p + 1;
                mma16816(acc[0][nA], Ah0, BH[0], BH[1]);
                mma16816(acc[1][nA], Ah1, BH[0], BH[1]);
                mma16816(acc[0][nA], Al0, BH[0], BH[1]);
                mma16816(acc[1][nA], Al1, BH[0], BH[1]);
                mma16816(acc[0][nA], Ah0, BL[0], BL[1]);
                mma16816(acc[1][nA], Ah1, BL[0], BL[1]);
                mma16816(acc[0][nB], Ah0, BH[2], BH[3]);
                mma16816(acc[1][nB], Ah1, BH[2], BH[3]);
                mma16816(acc[0][nB], Al0, BH[2], BH[3]);
                mma16816(acc[1][nB], Al1, BH[2], BH[3]);
                mma16816(acc[0][nB], Ah0, BL[2], BL[3]);
                mma16816(acc[1][nB], Ah1, BL[2], BL[3]);
            }
        }
    }

    // ---- final: s = relu(acc2 + b2) . W3, quad-shuffle reduce ----
#pragma unroll
    for (int mf = 0; mf < 2; mf++) {
        float pr = 0.f, pr8 = 0.f;
#pragma unroll
        for (int nf = 0; nf < 10; nf++) {
            const int n0 = wn * 80 + nf * 8 + tig * 2;
            const float2 bb = *(const float2*)(b2s + n0);
            const float2 ww = *(const float2*)(w3s + n0);
            pr  += fmaxf(acc[mf][nf][0] + bb.x, 0.f) * ww.x
                 + fmaxf(acc[mf][nf][1] + bb.y, 0.f) * ww.y;
            pr8 += fmaxf(acc[mf][nf][2] + bb.x, 0.f) * ww.x
                 + fmaxf(acc[mf][nf][3] + bb.y, 0.f) * ww.y;
        }
        pr  += __shfl_xor_sync(0xffffffffu, pr, 1);
        pr  += __shfl_xor_sync(0xffffffffu, pr, 2);
        pr8 += __shfl_xor_sync(0xffffffffu, pr8, 1);
        pr8 += __shfl_xor_sync(0xffffffffu, pr8, 2);
        if (tig == 0) {
            sred[wn * 128 + rowA + mf * 16]     = pr;
            sred[wn * 128 + rowA + mf * 16 + 8] = pr8;
        }
    }
    __syncthreads();

    if (tid < 128) {
        const float s = sred[tid] + sred[128 + tid];
        const int k = k0 + tid;
        if (k < WIN) {
            const int j = i - WIN + k;
            out[i * OUTW + k] = (j >= 0) ? (sm[i] + smjf[tid] + s + b3[0]) : 0.f;
        } else if (k == WIN) {
            out[i * OUTW + k] = 0.f;  // trailing epsilon column
        }
    }
}

// ---------------------------------------------------------------------------
extern "C" void kernel_launch(void* const* d_in, const int* in_sizes, int n_in,
                              void* d_out, int out_size) {
    const float* g  = (const float*)d_in[0];
    const float* sm = (const float*)d_in[1];
    const float* W1 = (const float*)d_in[2];
    const float* b1 = (const float*)d_in[3];
    const float* W2 = (const float*)d_in[4];
    const float* b2 = (const float*)d_in[5];
    const float* W3 = (const float*)d_in[6];
    const float* b3 = (const float*)d_in[7];
    float* out = (float*)d_out;

    cudaFuncSetAttribute(pair_mma_kernel, cudaFuncAttributeMaxDynamicSharedMemorySize,
                         SMEM_TOTAL);

    precompute_kernel<<<128, 256>>>(g, W1, b1);
    const int nprep = 8 * HPAD * 64 + 3 * HPAD * 64;
    wprep_kernel<<<(nprep + NTHREADS - 1) / NTHREADS, NTHREADS>>>(W1, W2);
    pair_mma_kernel<<<dim3(2, N_SPANS), NTHREADS, SMEM_TOTAL>>>(g, sm, b2, W3, b3, out);
}